// round 9
// baseline (speedup 1.0000x reference)
#include <cuda_runtime.h>
#include <cuda_fp16.h>
#include <cstdint>

#define NN 100000
#define NE 1600000
#define H  64

// ---------------- scratch (device globals; no allocation) ----------------
__device__ __half g_ew[1600000ull * 64];  // edge weights fp16, CSR-slot order [E,64]
__device__ int    g_cnt[NN];
__device__ int    g_off[NN + 1];
__device__ int    g_cur[NN];
__device__ int    g_src[NE];              // CSR-slot -> source node
__device__ int    g_pos[NE];              // edge e -> CSR slot
__device__ float  g_xlin[NN * H];
__device__ float  g_dinv[NN * H];
__device__ __half g_y[NN * H];            // fp16 gather operand
__device__ float  g_hagg[NN * H];
__device__ float  g_h[NN * H];

// ---------------- CSR build ----------------
__global__ void k_zero() {
    int i = blockIdx.x * blockDim.x + threadIdx.x;
    if (i < NN) g_cnt[i] = 0;
}

__global__ void k_count(const int* __restrict__ ei) {
    int e = blockIdx.x * blockDim.x + threadIdx.x;
    if (e < NE) {
        int c = ei[NE + e];
        if ((unsigned)c < (unsigned)NN) atomicAdd(&g_cnt[c], 1);
    }
}

__global__ void k_scan() {
    __shared__ int s[1024];
    int t = threadIdx.x;
    const int C = (NN + 1023) / 1024;
    int start = t * C; if (start > NN) start = NN;
    int end = start + C; if (end > NN) end = NN;
    int sum = 0;
    for (int i = start; i < end; i++) sum += g_cnt[i];
    s[t] = sum;
    __syncthreads();
    for (int d = 1; d < 1024; d <<= 1) {
        int v = (t >= d) ? s[t - d] : 0;
        __syncthreads();
        if (t >= d) s[t] += v;
        __syncthreads();
    }
    int run = (t == 0) ? 0 : s[t - 1];
    for (int i = start; i < end; i++) {
        g_off[i] = run; g_cur[i] = run; run += g_cnt[i];
    }
    if (t == 1023) g_off[NN] = run;
}

__global__ void k_fill(const int* __restrict__ ei) {
    int e = blockIdx.x * blockDim.x + threadIdx.x;
    if (e < NE) {
        int c = ei[NE + e];
        int r = ei[e];
        if ((unsigned)c >= (unsigned)NN || (unsigned)r >= (unsigned)NN) return;
        int p = atomicAdd(&g_cur[c], 1);
        g_src[p] = r;          // scattered
        g_pos[e] = p;          // coalesced
    }
}

// ---------------- mma.m16n8k16 f32 += f16 x f16 ----------------
__device__ __forceinline__ void mma16816(float c[4], const uint32_t a[4],
                                         uint32_t b0, uint32_t b1) {
    asm volatile(
        "mma.sync.aligned.m16n8k16.row.col.f32.f16.f16.f32 "
        "{%0,%1,%2,%3}, {%4,%5,%6,%7}, {%8,%9}, {%0,%1,%2,%3};"
        : "+f"(c[0]), "+f"(c[1]), "+f"(c[2]), "+f"(c[3])
        : "r"(a[0]), "r"(a[1]), "r"(a[2]), "r"(a[3]), "r"(b0), "r"(b1));
}

// ---------------- edge MLP (tensor-core): ew = relu( relu(ea@W1^T) @ W2^T ) ----------------
__global__ void __launch_bounds__(256) k_ew(const float* __restrict__ ea,
                                            const float* __restrict__ W1,
                                            const float* __restrict__ W2) {
    __shared__ __half h1s[256][72];
    __shared__ __half w2s[64][72];
    __shared__ float  w1s[64][8];
    __shared__ int    poss[256];
    int t = threadIdx.x;
    for (int i = t; i < 512; i += 256) ((float*)w1s)[i] = W1[i];
    for (int i = t; i < 4096; i += 256) w2s[i >> 6][i & 63] = __float2half(W2[i]);

    int base = blockIdx.x * 256;
    poss[t] = g_pos[base + t];
    float4 a0 = *(const float4*)&ea[(size_t)(base + t) * 8];
    float4 a1 = *(const float4*)&ea[(size_t)(base + t) * 8 + 4];
    __syncthreads();
#pragma unroll
    for (int ch = 0; ch < 64; ch += 2) {
        float4 p0 = *(const float4*)&w1s[ch][0];
        float4 p1 = *(const float4*)&w1s[ch][4];
        float4 q0 = *(const float4*)&w1s[ch + 1][0];
        float4 q1 = *(const float4*)&w1s[ch + 1][4];
        float v0 = a0.x * p0.x + a0.y * p0.y + a0.z * p0.z + a0.w * p0.w
                 + a1.x * p1.x + a1.y * p1.y + a1.z * p1.z + a1.w * p1.w;
        float v1 = a0.x * q0.x + a0.y * q0.y + a0.z * q0.z + a0.w * q0.w
                 + a1.x * q1.x + a1.y * q1.y + a1.z * q1.z + a1.w * q1.w;
        v0 = v0 > 0.f ? v0 : 0.f;
        v1 = v1 > 0.f ? v1 : 0.f;
        *(__half2*)&h1s[t][ch] = __floats2half2_rn(v0, v1);
    }
    __syncthreads();

    int w = t >> 5, l = t & 31;
    float c[2][8][4];
#pragma unroll
    for (int mt = 0; mt < 2; mt++)
#pragma unroll
        for (int nt = 0; nt < 8; nt++)
#pragma unroll
            for (int r = 0; r < 4; r++) c[mt][nt][r] = 0.f;

#pragma unroll
    for (int kc = 0; kc < 4; kc++) {
        int k0 = kc * 16 + (l & 3) * 2;
        uint32_t a[2][4];
#pragma unroll
        for (int mt = 0; mt < 2; mt++) {
            int r = w * 32 + mt * 16 + (l >> 2);
            a[mt][0] = *(const uint32_t*)&h1s[r][k0];
            a[mt][1] = *(const uint32_t*)&h1s[r + 8][k0];
            a[mt][2] = *(const uint32_t*)&h1s[r][k0 + 8];
            a[mt][3] = *(const uint32_t*)&h1s[r + 8][k0 + 8];
        }
#pragma unroll
        for (int nt = 0; nt < 8; nt++) {
            int nr = nt * 8 + (l >> 2);
            uint32_t b0 = *(const uint32_t*)&w2s[nr][k0];
            uint32_t b1 = *(const uint32_t*)&w2s[nr][k0 + 8];
            mma16816(c[0][nt], a[0], b0, b1);
            mma16816(c[1][nt], a[1], b0, b1);
        }
    }

#pragma unroll
    for (int mt = 0; mt < 2; mt++) {
        int m = w * 32 + mt * 16 + (l >> 2);
        size_t row0 = (size_t)poss[m] * 64;
        size_t row1 = (size_t)poss[m + 8] * 64;
#pragma unroll
        for (int nt = 0; nt < 8; nt++) {
            int n = nt * 8 + (l & 3) * 2;
            float v0 = c[mt][nt][0], v1 = c[mt][nt][1];
            float v2 = c[mt][nt][2], v3 = c[mt][nt][3];
            v0 = v0 > 0.f ? v0 : 0.f; v1 = v1 > 0.f ? v1 : 0.f;
            v2 = v2 > 0.f ? v2 : 0.f; v3 = v3 > 0.f ? v3 : 0.f;
            *(__half2*)&g_ew[row0 + n] = __floats2half2_rn(v0, v1);
            *(__half2*)&g_ew[row1 + n] = __floats2half2_rn(v2, v3);
        }
    }
}

// ---------------- degree / dinv + fused y0 (warp per node) ----------------
// y0 = dinv * relu(xlin) * wc0  (xlin produced concurrently on stream 2)
__global__ void __launch_bounds__(256) k_deg(const float* __restrict__ wc) {
    int w = (blockIdx.x * blockDim.x + threadIdx.x) >> 5;
    int lane = threadIdx.x & 31;
    if (w >= NN) return;
    int s = g_off[w], e = g_off[w + 1];
    const __half2* ewv = (const __half2*)g_ew;
    float2 d0 = make_float2(1.f, 1.f);        // self-loop weight
    float2 d1 = make_float2(0.f, 0.f);
    int p = s;
    for (; p + 2 <= e; p += 2) {
        float2 v0 = __half22float2(ewv[(size_t)p * 32 + lane]);
        float2 v1 = __half22float2(ewv[(size_t)(p + 1) * 32 + lane]);
        d0.x += v0.x; d0.y += v0.y;
        d1.x += v1.x; d1.y += v1.y;
    }
    if (p < e) {
        float2 v0 = __half22float2(ewv[(size_t)p * 32 + lane]);
        d0.x += v0.x; d0.y += v0.y;
    }
    float2 r; r.x = rsqrtf(d0.x + d1.x); r.y = rsqrtf(d0.y + d1.y);
    ((float2*)g_dinv)[(size_t)w * 32 + lane] = r;
    // fused y0
    float2 xv = ((const float2*)g_xlin)[(size_t)w * 32 + lane];
    float rv0 = xv.x > 0.f ? xv.x : 0.f;
    float rv1 = xv.y > 0.f ? xv.y : 0.f;
    ((__half2*)g_y)[(size_t)w * 32 + lane] =
        __floats2half2_rn(r.x * rv0 * wc[2 * lane], r.y * rv1 * wc[2 * lane + 1]);
}

// ---------------- aggregation (warp per node), unroll 8, int4 src, fp16 y ----------------
__global__ void __launch_bounds__(256) k_agg(const float* __restrict__ bc) {
    int w = (blockIdx.x * blockDim.x + threadIdx.x) >> 5;
    int lane = threadIdx.x & 31;
    if (w >= NN) return;
    int s = g_off[w], e = g_off[w + 1];
    const __half2* yv  = (const __half2*)g_y;
    const __half2* ewv = (const __half2*)g_ew;
    float2 a0 = __half22float2(yv[(size_t)w * 32 + lane]);   // self loop
    float2 a1 = make_float2(0.f, 0.f);
    float2 a2 = make_float2(0.f, 0.f);
    float2 a3 = make_float2(0.f, 0.f);
    float2 a4 = make_float2(0.f, 0.f);
    float2 a5 = make_float2(0.f, 0.f);
    float2 a6 = make_float2(0.f, 0.f);
    float2 a7 = make_float2(0.f, 0.f);
    int p = s;
    for (; p < e && (p & 3); p++) {
        int s0 = g_src[p];
        float2 f0 = __half22float2(ewv[(size_t)p * 32 + lane]);
        float2 y0 = __half22float2(yv[(size_t)s0 * 32 + lane]);
        a0.x = fmaf(f0.x, y0.x, a0.x); a0.y = fmaf(f0.y, y0.y, a0.y);
    }
    for (; p + 8 <= e; p += 8) {
        int4 sa = *(const int4*)&g_src[p];
        int4 sb = *(const int4*)&g_src[p + 4];
        __half2 h0 = ewv[(size_t)p * 32 + lane];
        __half2 h1 = ewv[(size_t)(p + 1) * 32 + lane];
        __half2 h2 = ewv[(size_t)(p + 2) * 32 + lane];
        __half2 h3 = ewv[(size_t)(p + 3) * 32 + lane];
        __half2 h4 = ewv[(size_t)(p + 4) * 32 + lane];
        __half2 h5 = ewv[(size_t)(p + 5) * 32 + lane];
        __half2 h6 = ewv[(size_t)(p + 6) * 32 + lane];
        __half2 h7 = ewv[(size_t)(p + 7) * 32 + lane];
        float2 y0 = __half22float2(yv[(size_t)sa.x * 32 + lane]);
        float2 y1 = __half22float2(yv[(size_t)sa.y * 32 + lane]);
        float2 y2 = __half22float2(yv[(size_t)sa.z * 32 + lane]);
        float2 y3 = __half22float2(yv[(size_t)sa.w * 32 + lane]);
        float2 y4 = __half22float2(yv[(size_t)sb.x * 32 + lane]);
        float2 y5 = __half22float2(yv[(size_t)sb.y * 32 + lane]);
        float2 y6 = __half22float2(yv[(size_t)sb.z * 32 + lane]);
        float2 y7 = __half22float2(yv[(size_t)sb.w * 32 + lane]);
        float2 f0 = __half22float2(h0), f1 = __half22float2(h1);
        float2 f2 = __half22float2(h2), f3 = __half22float2(h3);
        float2 f4 = __half22float2(h4), f5 = __half22float2(h5);
        float2 f6 = __half22float2(h6), f7 = __half22float2(h7);
        a0.x = fmaf(f0.x, y0.x, a0.x); a0.y = fmaf(f0.y, y0.y, a0.y);
        a1.x = fmaf(f1.x, y1.x, a1.x); a1.y = fmaf(f1.y, y1.y, a1.y);
        a2.x = fmaf(f2.x, y2.x, a2.x); a2.y = fmaf(f2.y, y2.y, a2.y);
        a3.x = fmaf(f3.x, y3.x, a3.x); a3.y = fmaf(f3.y, y3.y, a3.y);
        a4.x = fmaf(f4.x, y4.x, a4.x); a4.y = fmaf(f4.y, y4.y, a4.y);
        a5.x = fmaf(f5.x, y5.x, a5.x); a5.y = fmaf(f5.y, y5.y, a5.y);
        a6.x = fmaf(f6.x, y6.x, a6.x); a6.y = fmaf(f6.y, y6.y, a6.y);
        a7.x = fmaf(f7.x, y7.x, a7.x); a7.y = fmaf(f7.y, y7.y, a7.y);
    }
    for (; p + 4 <= e; p += 4) {
        int4 sv = *(const int4*)&g_src[p];
        __half2 h0 = ewv[(size_t)p * 32 + lane];
        __half2 h1 = ewv[(size_t)(p + 1) * 32 + lane];
        __half2 h2 = ewv[(size_t)(p + 2) * 32 + lane];
        __half2 h3 = ewv[(size_t)(p + 3) * 32 + lane];
        float2 y0 = __half22float2(yv[(size_t)sv.x * 32 + lane]);
        float2 y1 = __half22float2(yv[(size_t)sv.y * 32 + lane]);
        float2 y2 = __half22float2(yv[(size_t)sv.z * 32 + lane]);
        float2 y3 = __half22float2(yv[(size_t)sv.w * 32 + lane]);
        float2 f0 = __half22float2(h0), f1 = __half22float2(h1);
        float2 f2 = __half22float2(h2), f3 = __half22float2(h3);
        a0.x = fmaf(f0.x, y0.x, a0.x); a0.y = fmaf(f0.y, y0.y, a0.y);
        a1.x = fmaf(f1.x, y1.x, a1.x); a1.y = fmaf(f1.y, y1.y, a1.y);
        a2.x = fmaf(f2.x, y2.x, a2.x); a2.y = fmaf(f2.y, y2.y, a2.y);
        a3.x = fmaf(f3.x, y3.x, a3.x); a3.y = fmaf(f3.y, y3.y, a3.y);
    }
    for (; p < e; p++) {
        int s0 = g_src[p];
        float2 f0 = __half22float2(ewv[(size_t)p * 32 + lane]);
        float2 y0 = __half22float2(yv[(size_t)s0 * 32 + lane]);
        a0.x = fmaf(f0.x, y0.x, a0.x); a0.y = fmaf(f0.y, y0.y, a0.y);
    }
    float2 dv = ((const float2*)g_dinv)[(size_t)w * 32 + lane];
    float sx = ((a0.x + a1.x) + (a2.x + a3.x)) + ((a4.x + a5.x) + (a6.x + a7.x));
    float sy = ((a0.y + a1.y) + (a2.y + a3.y)) + ((a4.y + a5.y) + (a6.y + a7.y));
    float2 r;
    r.x = fmaf(dv.x, sx, bc[2 * lane]);
    r.y = fmaf(dv.y, sy, bc[2 * lane + 1]);
    ((float2*)g_hagg)[(size_t)w * 32 + lane] = r;
}

// ---------------- tensor-core GEMM: C[N,64] = A[N,128] @ W[64,128]^T ----------------
// mode 0: A0 = xin cols 0-63, A1 = xin cols 64-127 (lda 128), bias=bi, C=g_xlin
// mode 1: A0 = g_xlin, A1 = g_hagg (lda 64), resid=g_xlin, C=g_h
// ywc != null: fused y(fp16) = dinv*relu(C)*ywc.  Wo != null: fused final output.
__global__ void __launch_bounds__(256) k_gemm(const float* __restrict__ xin,
                                              const float* __restrict__ W,
                                              const float* __restrict__ bias,
                                              int mode,
                                              const float* __restrict__ ywc,
                                              const float* __restrict__ Wo,
                                              float* __restrict__ out) {
    __shared__ __half As[128][72];
    __shared__ __half Bs[64][136];
    int t = threadIdx.x;
    {   // vectorized W -> Bs (fp16)
        const float4* W4 = (const float4*)W;
        for (int i = t; i < 2048; i += 256) {
            float4 v = W4[i];
            int r = i >> 5, c4 = (i & 31) * 4;
            Bs[r][c4]     = __float2half(v.x);
            Bs[r][c4 + 1] = __float2half(v.y);
            Bs[r][c4 + 2] = __float2half(v.z);
            Bs[r][c4 + 3] = __float2half(v.w);
        }
    }

    const float *A0, *A1, *resid; float* C; int lda;
    if (mode == 0) { A0 = xin;    A1 = xin + 64; lda = 128; resid = 0;      C = g_xlin; }
    else           { A0 = g_xlin; A1 = g_hagg;   lda = 64;  resid = g_xlin; C = g_h;    }

    int bm = blockIdx.x * 128;
    int w = t >> 5, l = t & 31;
    float c[8][4];
#pragma unroll
    for (int nt = 0; nt < 8; nt++)
#pragma unroll
        for (int r = 0; r < 4; r++) c[nt][r] = 0.f;

    int lrow = t >> 1, lc0 = (t & 1) * 32;
    bool lvalid = (bm + lrow) < NN;

#pragma unroll
    for (int pass = 0; pass < 2; pass++) {
        const float* A = pass ? A1 : A0;
        __syncthreads();
        const float* srcp = &A[(size_t)(bm + lrow) * lda + lc0];
#pragma unroll
        for (int ch = 0; ch < 4; ch++) {
            float4 v0 = make_float4(0.f, 0.f, 0.f, 0.f), v1 = v0;
            if (lvalid) {
                v0 = *(const float4*)&srcp[ch * 8];
                v1 = *(const float4*)&srcp[ch * 8 + 4];
            }
            __half2 h0 = __floats2half2_rn(v0.x, v0.y);
            __half2 h1 = __floats2half2_rn(v0.z, v0.w);
            __half2 h2 = __floats2half2_rn(v1.x, v1.y);
            __half2 h3 = __floats2half2_rn(v1.z, v1.w);
            uint4 pk;
            pk.x = *(uint32_t*)&h0; pk.y = *(uint32_t*)&h1;
            pk.z = *(uint32_t*)&h2; pk.w = *(uint32_t*)&h3;
            *(uint4*)&As[lrow][lc0 + ch * 8] = pk;
        }
        __syncthreads();
#pragma unroll
        for (int kc = 0; kc < 4; kc++) {
            int k0 = kc * 16 + (l & 3) * 2;
            int row = w * 16 + (l >> 2);
            uint32_t a[4];
            a[0] = *(const uint32_t*)&As[row][k0];
            a[1] = *(const uint32_t*)&As[row + 8][k0];
            a[2] = *(const uint32_t*)&As[row][k0 + 8];
            a[3] = *(const uint32_t*)&As[row + 8][k0 + 8];
            int kb = pass * 64 + k0;
#pragma unroll
            for (int nt = 0; nt < 8; nt++) {
                int nr = nt * 8 + (l >> 2);
                uint32_t b0 = *(const uint32_t*)&Bs[nr][kb];
                uint32_t b1 = *(const uint32_t*)&Bs[nr][kb + 8];
                mma16816(c[nt], a, b0, b1);
            }
        }
    }

    int m0 = bm + w * 16 + (l >> 2);
    int n0 = (l & 3) * 2;

    if (Wo) {
        float oacc[2] = {0.f, 0.f};
#pragma unroll
        for (int nt = 0; nt < 8; nt++) {
            int n = nt * 8 + n0;
            float wx0 = Wo[n], wx1 = Wo[n + 1];
            float wh0 = Wo[64 + n], wh1 = Wo[64 + n + 1];
#pragma unroll
            for (int rr = 0; rr < 2; rr++) {
                int m = m0 + rr * 8;
                if (m >= NN) continue;
                float2 rv = *(const float2*)&resid[(size_t)m * 64 + n];
                float h0 = c[nt][rr * 2] + rv.x;
                float h1 = c[nt][rr * 2 + 1] + rv.y;
                h0 = h0 > 0.f ? h0 : 0.f;
                h1 = h1 > 0.f ? h1 : 0.f;
                oacc[rr] += rv.x * wx0 + rv.y * wx1 + h0 * wh0 + h1 * wh1;
            }
        }
#pragma unroll
        for (int rr = 0; rr < 2; rr++) {
            oacc[rr] += __shfl_xor_sync(0xffffffffu, oacc[rr], 1);
            oacc[rr] += __shfl_xor_sync(0xffffffffu, oacc[rr], 2);
        }
        if ((l & 3) == 0) {
            if (m0 < NN)     out[m0]     = oacc[0];
            if (m0 + 8 < NN) out[m0 + 8] = oacc[1];
        }
        return;
    }

#pragma unroll
    for (int nt = 0; nt < 8; nt++) {
        int n = nt * 8 + n0;
#pragma unroll
        for (int rr = 0; rr < 2; rr++) {
            int m = m0 + rr * 8;
            if (m >= NN) continue;
            float v0 = c[nt][rr * 2], v1 = c[nt][rr * 2 + 1];
            if (bias) { v0 += bias[n]; v1 += bias[n + 1]; }
            if (resid) {
                float2 rv = *(const float2*)&resid[(size_t)m * 64 + n];
                v0 += rv.x; v1 += rv.y;
            }
            float2 ov; ov.x = v0; ov.y = v1;
            *(float2*)&C[(size_t)m * 64 + n] = ov;
            if (ywc) {
                float2 dv = *(const float2*)&g_dinv[(size_t)m * 64 + n];
                float r0 = v0 > 0.f ? v0 : 0.f;
                float r1 = v1 > 0.f ? v1 : 0.f;
                *(__half2*)&g_y[(size_t)m * 64 + n] =
                    __floats2half2_rn(dv.x * r0 * ywc[n], dv.y * r1 * ywc[n + 1]);
            }
        }
    }
}

// ---------------- host ----------------
static cudaStream_t s_aux = nullptr;
static cudaEvent_t  s_evFork = nullptr, s_evJoin = nullptr;

extern "C" void kernel_launch(void* const* d_in, const int* in_sizes, int n_in,
                              void* d_out, int out_size) {
    const float* x  = (const float*)d_in[0];
    const int*   ei = (const int*)d_in[1];     // int32 [2, E]
    const float* ea = (const float*)d_in[2];
    const float* W1 = (const float*)d_in[3];
    const float* W2 = (const float*)d_in[4];
    const float* Wi = (const float*)d_in[5];
    const float* bi = (const float*)d_in[6];
    const float* wc = (const float*)d_in[7];
    const float* bc = (const float*)d_in[8];
    const float* Wl = (const float*)d_in[9];
    const float* Wo = (const float*)d_in[10];
    float* out = (float*)d_out;

    if (!s_aux) {   // host-side infra, created once; per-call work is identical
        cudaStreamCreateWithFlags(&s_aux, cudaStreamNonBlocking);
        cudaEventCreateWithFlags(&s_evFork, cudaEventDisableTiming);
        cudaEventCreateWithFlags(&s_evJoin, cudaEventDisableTiming);
    }

    const int WPB = 8;

    // fork: gemm0 (xlin = x@Wi^T + bi) runs concurrently with CSR build + k_ew
    cudaEventRecord(s_evFork, 0);
    cudaStreamWaitEvent(s_aux, s_evFork, 0);
    k_gemm<<<(NN + 127) / 128, 256, 0, s_aux>>>(x, Wi, bi, 0, nullptr, nullptr, nullptr);
    cudaEventRecord(s_evJoin, s_aux);

    k_zero<<<(NN + 1023) / 1024, 1024>>>();
    k_count<<<(NE + 255) / 256, 256>>>(ei);
    k_scan<<<1, 1024>>>();
    k_fill<<<(NE + 255) / 256, 256>>>(ei);
    k_ew<<<NE / 256, 256>>>(ea, W1, W2);

    // join: k_deg consumes g_xlin (y0 epilogue) and g_ew
    cudaStreamWaitEvent(0, s_evJoin, 0);
    k_deg<<<(NN + WPB - 1) / WPB, 256>>>(wc);
    for (int l = 0; l < 3; l++) {
        k_agg<<<(NN + WPB - 1) / WPB, 256>>>(bc + l * 64);
        k_gemm<<<(NN + 127) / 128, 256>>>(x, Wl + l * 64 * 128, nullptr, 1,
                                          l < 2 ? wc + (l + 1) * 64 : nullptr,
                                          l == 2 ? Wo : nullptr,
                                          l == 2 ? out : nullptr);
    }
}

// round 10
// speedup vs baseline: 1.3300x; 1.3300x over previous
#include <cuda_runtime.h>
#include <cuda_fp16.h>
#include <cstdint>

#define NN 100000
#define NE 1600000
#define H  64
#define SCAN_B 1024
#define NBLK ((NN + SCAN_B - 1) / SCAN_B)   // 98

// ---------------- scratch (device globals; no allocation) ----------------
__device__ __half g_ew[1600000ull * 64];  // edge weights fp16, CSR-slot order [E,64]
__device__ int    g_cnt[NN];
__device__ int    g_off[NN + 1];
__device__ int    g_cur[NN];
__device__ int    g_src[NE];              // CSR-slot -> source node
__device__ int    g_pos[NE];              // edge e -> CSR slot
__device__ int    g_bsum[NBLK];
__device__ int    g_boff[NBLK];
__device__ float  g_xlin[NN * H];
__device__ float  g_dinv[NN * H];
__device__ __half g_y[NN * H];            // fp16 gather operand
__device__ float  g_hagg[NN * H];
__device__ float  g_h[NN * H];

// ---------------- CSR build ----------------
__global__ void k_zero() {
    int i = blockIdx.x * blockDim.x + threadIdx.x;
    if (i < NN) g_cnt[i] = 0;
}

__global__ void k_count(const int* __restrict__ ei) {
    int e = blockIdx.x * blockDim.x + threadIdx.x;
    if (e < NE) {
        int c = ei[NE + e];
        if ((unsigned)c < (unsigned)NN) atomicAdd(&g_cnt[c], 1);
    }
}

// ---- hierarchical scan: per-block sums -> top scan -> per-block apply ----
__global__ void __launch_bounds__(1024) k_scan_sum() {
    __shared__ int s[1024];
    int t = threadIdx.x, b = blockIdx.x;
    int i = b * SCAN_B + t;
    s[t] = (i < NN) ? g_cnt[i] : 0;
    __syncthreads();
#pragma unroll
    for (int d = 512; d > 0; d >>= 1) {
        if (t < d) s[t] += s[t + d];
        __syncthreads();
    }
    if (t == 0) g_bsum[b] = s[0];
}

__global__ void __launch_bounds__(128) k_scan_top() {
    __shared__ int s[128];
    int t = threadIdx.x;
    int v = (t < NBLK) ? g_bsum[t] : 0;
    s[t] = v;
    __syncthreads();
#pragma unroll
    for (int d = 1; d < 128; d <<= 1) {
        int u = (t >= d) ? s[t - d] : 0;
        __syncthreads();
        s[t] += u;
        __syncthreads();
    }
    if (t < NBLK) g_boff[t] = s[t] - v;          // exclusive
    if (t == NBLK - 1) g_off[NN] = s[t];         // total
}

__global__ void __launch_bounds__(1024) k_scan_apply() {
    __shared__ int s[1024];
    int t = threadIdx.x, b = blockIdx.x;
    int i = b * SCAN_B + t;
    int v = (i < NN) ? g_cnt[i] : 0;
    s[t] = v;
    __syncthreads();
#pragma unroll
    for (int d = 1; d < 1024; d <<= 1) {
        int u = (t >= d) ? s[t - d] : 0;
        __syncthreads();
        s[t] += u;
        __syncthreads();
    }
    if (i < NN) {
        int off = g_boff[b] + s[t] - v;          // exclusive
        g_off[i] = off;
        g_cur[i] = off;
    }
}

__global__ void k_fill(const int* __restrict__ ei) {
    int e = blockIdx.x * blockDim.x + threadIdx.x;
    if (e < NE) {
        int c = ei[NE + e];
        int r = ei[e];
        if ((unsigned)c >= (unsigned)NN || (unsigned)r >= (unsigned)NN) return;
        int p = atomicAdd(&g_cur[c], 1);
        g_src[p] = r;          // scattered
        g_pos[e] = p;          // coalesced
    }
}

// ---------------- mma.m16n8k16 f32 += f16 x f16 ----------------
__device__ __forceinline__ void mma16816(float c[4], const uint32_t a[4],
                                         uint32_t b0, uint32_t b1) {
    asm volatile(
        "mma.sync.aligned.m16n8k16.row.col.f32.f16.f16.f32 "
        "{%0,%1,%2,%3}, {%4,%5,%6,%7}, {%8,%9}, {%0,%1,%2,%3};"
        : "+f"(c[0]), "+f"(c[1]), "+f"(c[2]), "+f"(c[3])
        : "r"(a[0]), "r"(a[1]), "r"(a[2]), "r"(a[3]), "r"(b0), "r"(b1));
}

// ---------------- edge MLP (tensor-core): ew = relu( relu(ea@W1^T) @ W2^T ) ----------------
__global__ void __launch_bounds__(256) k_ew(const float* __restrict__ ea,
                                            const float* __restrict__ W1,
                                            const float* __restrict__ W2) {
    __shared__ __half h1s[256][72];
    __shared__ __half w2s[64][72];
    __shared__ float  w1s[64][8];
    __shared__ int    poss[256];
    int t = threadIdx.x;
    for (int i = t; i < 512; i += 256) ((float*)w1s)[i] = W1[i];
    for (int i = t; i < 4096; i += 256) w2s[i >> 6][i & 63] = __float2half(W2[i]);

    int base = blockIdx.x * 256;
    poss[t] = g_pos[base + t];
    float4 a0 = *(const float4*)&ea[(size_t)(base + t) * 8];
    float4 a1 = *(const float4*)&ea[(size_t)(base + t) * 8 + 4];
    __syncthreads();
#pragma unroll
    for (int ch = 0; ch < 64; ch += 2) {
        float4 p0 = *(const float4*)&w1s[ch][0];
        float4 p1 = *(const float4*)&w1s[ch][4];
        float4 q0 = *(const float4*)&w1s[ch + 1][0];
        float4 q1 = *(const float4*)&w1s[ch + 1][4];
        float v0 = a0.x * p0.x + a0.y * p0.y + a0.z * p0.z + a0.w * p0.w
                 + a1.x * p1.x + a1.y * p1.y + a1.z * p1.z + a1.w * p1.w;
        float v1 = a0.x * q0.x + a0.y * q0.y + a0.z * q0.z + a0.w * q0.w
                 + a1.x * q1.x + a1.y * q1.y + a1.z * q1.z + a1.w * q1.w;
        v0 = v0 > 0.f ? v0 : 0.f;
        v1 = v1 > 0.f ? v1 : 0.f;
        *(__half2*)&h1s[t][ch] = __floats2half2_rn(v0, v1);
    }
    __syncthreads();

    int w = t >> 5, l = t & 31;
    float c[2][8][4];
#pragma unroll
    for (int mt = 0; mt < 2; mt++)
#pragma unroll
        for (int nt = 0; nt < 8; nt++)
#pragma unroll
            for (int r = 0; r < 4; r++) c[mt][nt][r] = 0.f;

#pragma unroll
    for (int kc = 0; kc < 4; kc++) {
        int k0 = kc * 16 + (l & 3) * 2;
        uint32_t a[2][4];
#pragma unroll
        for (int mt = 0; mt < 2; mt++) {
            int r = w * 32 + mt * 16 + (l >> 2);
            a[mt][0] = *(const uint32_t*)&h1s[r][k0];
            a[mt][1] = *(const uint32_t*)&h1s[r + 8][k0];
            a[mt][2] = *(const uint32_t*)&h1s[r][k0 + 8];
            a[mt][3] = *(const uint32_t*)&h1s[r + 8][k0 + 8];
        }
#pragma unroll
        for (int nt = 0; nt < 8; nt++) {
            int nr = nt * 8 + (l >> 2);
            uint32_t b0 = *(const uint32_t*)&w2s[nr][k0];
            uint32_t b1 = *(const uint32_t*)&w2s[nr][k0 + 8];
            mma16816(c[0][nt], a[0], b0, b1);
            mma16816(c[1][nt], a[1], b0, b1);
        }
    }

#pragma unroll
    for (int mt = 0; mt < 2; mt++) {
        int m = w * 32 + mt * 16 + (l >> 2);
        size_t row0 = (size_t)poss[m] * 64;
        size_t row1 = (size_t)poss[m + 8] * 64;
#pragma unroll
        for (int nt = 0; nt < 8; nt++) {
            int n = nt * 8 + (l & 3) * 2;
            float v0 = c[mt][nt][0], v1 = c[mt][nt][1];
            float v2 = c[mt][nt][2], v3 = c[mt][nt][3];
            v0 = v0 > 0.f ? v0 : 0.f; v1 = v1 > 0.f ? v1 : 0.f;
            v2 = v2 > 0.f ? v2 : 0.f; v3 = v3 > 0.f ? v3 : 0.f;
            *(__half2*)&g_ew[row0 + n] = __floats2half2_rn(v0, v1);
            *(__half2*)&g_ew[row1 + n] = __floats2half2_rn(v2, v3);
        }
    }
}

// ---------------- degree / dinv (warp per node, half2, unroll 2) ----------------
__global__ void __launch_bounds__(256) k_deg() {
    int w = (blockIdx.x * blockDim.x + threadIdx.x) >> 5;
    int lane = threadIdx.x & 31;
    if (w >= NN) return;
    int s = g_off[w], e = g_off[w + 1];
    const __half2* ewv = (const __half2*)g_ew;
    float2 d0 = make_float2(1.f, 1.f);        // self-loop weight
    float2 d1 = make_float2(0.f, 0.f);
    int p = s;
    for (; p + 2 <= e; p += 2) {
        float2 v0 = __half22float2(ewv[(size_t)p * 32 + lane]);
        float2 v1 = __half22float2(ewv[(size_t)(p + 1) * 32 + lane]);
        d0.x += v0.x; d0.y += v0.y;
        d1.x += v1.x; d1.y += v1.y;
    }
    if (p < e) {
        float2 v0 = __half22float2(ewv[(size_t)p * 32 + lane]);
        d0.x += v0.x; d0.y += v0.y;
    }
    float2 r; r.x = rsqrtf(d0.x + d1.x); r.y = rsqrtf(d0.y + d1.y);
    ((float2*)g_dinv)[(size_t)w * 32 + lane] = r;
}

// ---------------- aggregation (warp per node), unroll 4, int4 src, fp16 y ----------------
__global__ void __launch_bounds__(256) k_agg(const float* __restrict__ bc) {
    int w = (blockIdx.x * blockDim.x + threadIdx.x) >> 5;
    int lane = threadIdx.x & 31;
    if (w >= NN) return;
    int s = g_off[w], e = g_off[w + 1];
    const __half2* yv  = (const __half2*)g_y;
    const __half2* ewv = (const __half2*)g_ew;
    float2 a0 = __half22float2(yv[(size_t)w * 32 + lane]);   // self loop
    float2 a1 = make_float2(0.f, 0.f);
    float2 a2 = make_float2(0.f, 0.f);
    float2 a3 = make_float2(0.f, 0.f);
    int p = s;
    for (; p < e && (p & 3); p++) {
        int s0 = g_src[p];
        float2 f0 = __half22float2(ewv[(size_t)p * 32 + lane]);
        float2 y0 = __half22float2(yv[(size_t)s0 * 32 + lane]);
        a0.x = fmaf(f0.x, y0.x, a0.x); a0.y = fmaf(f0.y, y0.y, a0.y);
    }
    for (; p + 4 <= e; p += 4) {
        int4 sv = *(const int4*)&g_src[p];
        __half2 h0 = ewv[(size_t)p * 32 + lane];
        __half2 h1 = ewv[(size_t)(p + 1) * 32 + lane];
        __half2 h2 = ewv[(size_t)(p + 2) * 32 + lane];
        __half2 h3 = ewv[(size_t)(p + 3) * 32 + lane];
        float2 y0 = __half22float2(yv[(size_t)sv.x * 32 + lane]);
        float2 y1 = __half22float2(yv[(size_t)sv.y * 32 + lane]);
        float2 y2 = __half22float2(yv[(size_t)sv.z * 32 + lane]);
        float2 y3 = __half22float2(yv[(size_t)sv.w * 32 + lane]);
        float2 f0 = __half22float2(h0), f1 = __half22float2(h1);
        float2 f2 = __half22float2(h2), f3 = __half22float2(h3);
        a0.x = fmaf(f0.x, y0.x, a0.x); a0.y = fmaf(f0.y, y0.y, a0.y);
        a1.x = fmaf(f1.x, y1.x, a1.x); a1.y = fmaf(f1.y, y1.y, a1.y);
        a2.x = fmaf(f2.x, y2.x, a2.x); a2.y = fmaf(f2.y, y2.y, a2.y);
        a3.x = fmaf(f3.x, y3.x, a3.x); a3.y = fmaf(f3.y, y3.y, a3.y);
    }
    for (; p < e; p++) {
        int s0 = g_src[p];
        float2 f0 = __half22float2(ewv[(size_t)p * 32 + lane]);
        float2 y0 = __half22float2(yv[(size_t)s0 * 32 + lane]);
        a0.x = fmaf(f0.x, y0.x, a0.x); a0.y = fmaf(f0.y, y0.y, a0.y);
    }
    float2 dv = ((const float2*)g_dinv)[(size_t)w * 32 + lane];
    float2 r;
    r.x = fmaf(dv.x, (a0.x + a1.x) + (a2.x + a3.x), bc[2 * lane]);
    r.y = fmaf(dv.y, (a0.y + a1.y) + (a2.y + a3.y), bc[2 * lane + 1]);
    ((float2*)g_hagg)[(size_t)w * 32 + lane] = r;
}

// ---------------- tensor-core GEMM: C[N,64] = A[N,128] @ W[64,128]^T ----------------
// mode 0: A0 = xin cols 0-63, A1 = xin cols 64-127 (lda 128), bias=bi, C=g_xlin
// mode 1: A0 = g_xlin, A1 = g_hagg (lda 64), resid=g_xlin, C=g_h
// ywc != null: fused y(fp16) = dinv*relu(C)*ywc.  Wo != null: fused final output.
__global__ void __launch_bounds__(256) k_gemm(const float* __restrict__ xin,
                                              const float* __restrict__ W,
                                              const float* __restrict__ bias,
                                              int mode,
                                              const float* __restrict__ ywc,
                                              const float* __restrict__ Wo,
                                              float* __restrict__ out) {
    __shared__ __half As[128][72];
    __shared__ __half Bs[64][136];
    int t = threadIdx.x;
    for (int i = t; i < 8192; i += 256) Bs[i >> 7][i & 127] = __float2half(W[i]);

    const float *A0, *A1, *resid; float* C; int lda;
    if (mode == 0) { A0 = xin;    A1 = xin + 64; lda = 128; resid = 0;      C = g_xlin; }
    else           { A0 = g_xlin; A1 = g_hagg;   lda = 64;  resid = g_xlin; C = g_h;    }

    int bm = blockIdx.x * 128;
    int w = t >> 5, l = t & 31;
    float c[8][4];
#pragma unroll
    for (int nt = 0; nt < 8; nt++)
#pragma unroll
        for (int r = 0; r < 4; r++) c[nt][r] = 0.f;

    int lrow = t >> 1, lc0 = (t & 1) * 32;
    bool lvalid = (bm + lrow) < NN;

#pragma unroll
    for (int pass = 0; pass < 2; pass++) {
        const float* A = pass ? A1 : A0;
        __syncthreads();
        const float* srcp = &A[(size_t)(bm + lrow) * lda + lc0];
#pragma unroll
        for (int ch = 0; ch < 4; ch++) {
            float4 v0 = make_float4(0.f, 0.f, 0.f, 0.f), v1 = v0;
            if (lvalid) {
                v0 = *(const float4*)&srcp[ch * 8];
                v1 = *(const float4*)&srcp[ch * 8 + 4];
            }
            __half2 h0 = __floats2half2_rn(v0.x, v0.y);
            __half2 h1 = __floats2half2_rn(v0.z, v0.w);
            __half2 h2 = __floats2half2_rn(v1.x, v1.y);
            __half2 h3 = __floats2half2_rn(v1.z, v1.w);
            uint4 pk;
            pk.x = *(uint32_t*)&h0; pk.y = *(uint32_t*)&h1;
            pk.z = *(uint32_t*)&h2; pk.w = *(uint32_t*)&h3;
            *(uint4*)&As[lrow][lc0 + ch * 8] = pk;
        }
        __syncthreads();
#pragma unroll
        for (int kc = 0; kc < 4; kc++) {
            int k0 = kc * 16 + (l & 3) * 2;
            int row = w * 16 + (l >> 2);
            uint32_t a[4];
            a[0] = *(const uint32_t*)&As[row][k0];
            a[1] = *(const uint32_t*)&As[row + 8][k0];
            a[2] = *(const uint32_t*)&As[row][k0 + 8];
            a[3] = *(const uint32_t*)&As[row + 8][k0 + 8];
            int kb = pass * 64 + k0;
#pragma unroll
            for (int nt = 0; nt < 8; nt++) {
                int nr = nt * 8 + (l >> 2);
                uint32_t b0 = *(const uint32_t*)&Bs[nr][kb];
                uint32_t b1 = *(const uint32_t*)&Bs[nr][kb + 8];
                mma16816(c[nt], a, b0, b1);
            }
        }
    }

    int m0 = bm + w * 16 + (l >> 2);
    int n0 = (l & 3) * 2;

    if (Wo) {
        float oacc[2] = {0.f, 0.f};
#pragma unroll
        for (int nt = 0; nt < 8; nt++) {
            int n = nt * 8 + n0;
            float wx0 = Wo[n], wx1 = Wo[n + 1];
            float wh0 = Wo[64 + n], wh1 = Wo[64 + n + 1];
#pragma unroll
            for (int rr = 0; rr < 2; rr++) {
                int m = m0 + rr * 8;
                if (m >= NN) continue;
                float2 rv = *(const float2*)&resid[(size_t)m * 64 + n];
                float h0 = c[nt][rr * 2] + rv.x;
                float h1 = c[nt][rr * 2 + 1] + rv.y;
                h0 = h0 > 0.f ? h0 : 0.f;
                h1 = h1 > 0.f ? h1 : 0.f;
                oacc[rr] += rv.x * wx0 + rv.y * wx1 + h0 * wh0 + h1 * wh1;
            }
        }
#pragma unroll
        for (int rr = 0; rr < 2; rr++) {
            oacc[rr] += __shfl_xor_sync(0xffffffffu, oacc[rr], 1);
            oacc[rr] += __shfl_xor_sync(0xffffffffu, oacc[rr], 2);
        }
        if ((l & 3) == 0) {
            if (m0 < NN)     out[m0]     = oacc[0];
            if (m0 + 8 < NN) out[m0 + 8] = oacc[1];
        }
        return;
    }

#pragma unroll
    for (int nt = 0; nt < 8; nt++) {
        int n = nt * 8 + n0;
#pragma unroll
        for (int rr = 0; rr < 2; rr++) {
            int m = m0 + rr * 8;
            if (m >= NN) continue;
            float v0 = c[nt][rr * 2], v1 = c[nt][rr * 2 + 1];
            if (bias) { v0 += bias[n]; v1 += bias[n + 1]; }
            if (resid) {
                float2 rv = *(const float2*)&resid[(size_t)m * 64 + n];
                v0 += rv.x; v1 += rv.y;
            }
            float2 ov; ov.x = v0; ov.y = v1;
            *(float2*)&C[(size_t)m * 64 + n] = ov;
            if (ywc) {
                float2 dv = *(const float2*)&g_dinv[(size_t)m * 64 + n];
                float r0 = v0 > 0.f ? v0 : 0.f;
                float r1 = v1 > 0.f ? v1 : 0.f;
                *(__half2*)&g_y[(size_t)m * 64 + n] =
                    __floats2half2_rn(dv.x * r0 * ywc[n], dv.y * r1 * ywc[n + 1]);
            }
        }
    }
}

// ---------------- host ----------------
extern "C" void kernel_launch(void* const* d_in, const int* in_sizes, int n_in,
                              void* d_out, int out_size) {
    const float* x  = (const float*)d_in[0];
    const int*   ei = (const int*)d_in[1];     // int32 [2, E]
    const float* ea = (const float*)d_in[2];
    const float* W1 = (const float*)d_in[3];
    const float* W2 = (const float*)d_in[4];
    const float* Wi = (const float*)d_in[5];
    const float* bi = (const float*)d_in[6];
    const float* wc = (const float*)d_in[7];
    const float* bc = (const float*)d_in[8];
    const float* Wl = (const float*)d_in[9];
    const float* Wo = (const float*)d_in[10];
    float* out = (float*)d_out;

    const int WPB = 8;
    k_zero<<<(NN + 1023) / 1024, 1024>>>();
    k_count<<<(NE + 255) / 256, 256>>>(ei);
    k_scan_sum<<<NBLK, 1024>>>();
    k_scan_top<<<1, 128>>>();
    k_scan_apply<<<NBLK, 1024>>>();
    k_fill<<<(NE + 255) / 256, 256>>>(ei);
    k_ew<<<NE / 256, 256>>>(ea, W1, W2);
    k_deg<<<(NN + WPB - 1) / WPB, 256>>>();
    k_gemm<<<(NN + 127) / 128, 256>>>(x, Wi, bi, 0, wc, nullptr, nullptr);
    for (int l = 0; l < 3; l++) {
        k_agg<<<(NN + WPB - 1) / WPB, 256>>>(bc + l * 64);
        k_gemm<<<(NN + 127) / 128, 256>>>(x, Wl + l * 64 * 128, nullptr, 1,
                                          l < 2 ? wc + (l + 1) * 64 : nullptr,
                                          l == 2 ? Wo : nullptr,
                                          l == 2 ? out : nullptr);
    }
}

// round 11
// speedup vs baseline: 1.4136x; 1.0629x over previous
#include <cuda_runtime.h>
#include <cuda_fp16.h>
#include <cstdint>

#define NN 100000
#define NE 1600000
#define H  64
#define SCAN_B 1024
#define NBLK ((NN + SCAN_B - 1) / SCAN_B)   // 98

// ---------------- scratch (device globals; no allocation) ----------------
__device__ __half g_ew[1600000ull * 64];  // edge weights fp16, CSR-slot order [E,64]
__device__ int    g_cnt[NN];
__device__ int    g_off[NN + 1];
__device__ int    g_cur[NN];
__device__ int    g_src[NE];              // CSR-slot -> source node
__device__ int    g_pos[NE];              // edge e -> CSR slot
__device__ int    g_bsum[NBLK];
__device__ int    g_boff[NBLK];
__device__ float  g_xlin[NN * H];
__device__ float  g_dinv[NN * H];
__device__ __half g_y[NN * H];            // fp16 gather operand
__device__ float  g_hagg[NN * H];
__device__ float  g_h[NN * H];

// ---------------- CSR build ----------------
__global__ void k_zero() {
    int i = blockIdx.x * blockDim.x + threadIdx.x;
    if (i < NN) g_cnt[i] = 0;
}

__global__ void k_count(const int* __restrict__ ei) {
    int e = blockIdx.x * blockDim.x + threadIdx.x;
    if (e < NE) {
        int c = ei[NE + e];
        if ((unsigned)c < (unsigned)NN) atomicAdd(&g_cnt[c], 1);
    }
}

// ---- hierarchical scan ----
__global__ void __launch_bounds__(1024) k_scan_sum() {
    __shared__ int s[1024];
    int t = threadIdx.x, b = blockIdx.x;
    int i = b * SCAN_B + t;
    s[t] = (i < NN) ? g_cnt[i] : 0;
    __syncthreads();
#pragma unroll
    for (int d = 512; d > 0; d >>= 1) {
        if (t < d) s[t] += s[t + d];
        __syncthreads();
    }
    if (t == 0) g_bsum[b] = s[0];
}

__global__ void __launch_bounds__(128) k_scan_top() {
    __shared__ int s[128];
    int t = threadIdx.x;
    int v = (t < NBLK) ? g_bsum[t] : 0;
    s[t] = v;
    __syncthreads();
#pragma unroll
    for (int d = 1; d < 128; d <<= 1) {
        int u = (t >= d) ? s[t - d] : 0;
        __syncthreads();
        s[t] += u;
        __syncthreads();
    }
    if (t < NBLK) g_boff[t] = s[t] - v;
    if (t == NBLK - 1) g_off[NN] = s[t];
}

__global__ void __launch_bounds__(1024) k_scan_apply() {
    __shared__ int s[1024];
    int t = threadIdx.x, b = blockIdx.x;
    int i = b * SCAN_B + t;
    int v = (i < NN) ? g_cnt[i] : 0;
    s[t] = v;
    __syncthreads();
#pragma unroll
    for (int d = 1; d < 1024; d <<= 1) {
        int u = (t >= d) ? s[t - d] : 0;
        __syncthreads();
        s[t] += u;
        __syncthreads();
    }
    if (i < NN) {
        int off = g_boff[b] + s[t] - v;
        g_off[i] = off;
        g_cur[i] = off;
    }
}

__global__ void k_fill(const int* __restrict__ ei) {
    int e = blockIdx.x * blockDim.x + threadIdx.x;
    if (e < NE) {
        int c = ei[NE + e];
        int r = ei[e];
        if ((unsigned)c >= (unsigned)NN || (unsigned)r >= (unsigned)NN) return;
        int p = atomicAdd(&g_cur[c], 1);
        g_src[p] = r;
        g_pos[e] = p;
    }
}

// ---------------- mma.m16n8k16 f32 += f16 x f16 ----------------
__device__ __forceinline__ void mma16816(float c[4], const uint32_t a[4],
                                         uint32_t b0, uint32_t b1) {
    asm volatile(
        "mma.sync.aligned.m16n8k16.row.col.f32.f16.f16.f32 "
        "{%0,%1,%2,%3}, {%4,%5,%6,%7}, {%8,%9}, {%0,%1,%2,%3};"
        : "+f"(c[0]), "+f"(c[1]), "+f"(c[2]), "+f"(c[3])
        : "r"(a[0]), "r"(a[1]), "r"(a[2]), "r"(a[3]), "r"(b0), "r"(b1));
}

// ---------------- edge MLP, BOTH stages on tensor cores ----------------
// stage 1: h1[256,64] = relu( ea[256,8] @ W1^T )  (K=16 zero-padded MMA)
// stage 2: ew[256,64] = relu( h1 @ W2^T )
// eas aliases h1s buffer (barrier-separated lifetimes).
__global__ void __launch_bounds__(256) k_ew(const float* __restrict__ ea,
                                            const float* __restrict__ W1,
                                            const float* __restrict__ W2) {
    __shared__ char  buf[256 * 72 * 2];          // 36864 B: eas then h1s
    __shared__ __half w1h[64][16];               // 2048 B (cols 8..15 zero)
    __shared__ __half w2s[64][72];               // 9216 B
    __half (*eas)[24] = (__half(*)[24])buf;      // [256][24], cols 8..15 zero
    __half (*h1s)[72] = (__half(*)[72])buf;      // [256][72]

    int t = threadIdx.x;
    // weights -> smem fp16
    for (int i = t; i < 512; i += 256) {
        w1h[i >> 3][i & 7] = __float2half(W1[i]);
        w1h[i >> 3][8 + (i & 7)] = __float2half(0.f);
    }
    for (int i = t; i < 4096; i += 256) w2s[i >> 6][i & 63] = __float2half(W2[i]);

    int base = blockIdx.x * 256;
    int w = t >> 5, l = t & 31;
    int p_own = g_pos[base + t];                 // CSR slot for this thread's edge

    // ea row -> eas fp16 (cols 8..15 zeroed)
    {
        float4 a0 = *(const float4*)&ea[(size_t)(base + t) * 8];
        float4 a1 = *(const float4*)&ea[(size_t)(base + t) * 8 + 4];
        __half2* er = (__half2*)&eas[t][0];
        er[0] = __floats2half2_rn(a0.x, a0.y);
        er[1] = __floats2half2_rn(a0.z, a0.w);
        er[2] = __floats2half2_rn(a1.x, a1.y);
        er[3] = __floats2half2_rn(a1.z, a1.w);
        __half2 z = __floats2half2_rn(0.f, 0.f);
        er[4] = z; er[5] = z; er[6] = z; er[7] = z;
    }
    __syncthreads();

    float c[2][8][4];
#pragma unroll
    for (int mt = 0; mt < 2; mt++)
#pragma unroll
        for (int nt = 0; nt < 8; nt++)
#pragma unroll
            for (int r = 0; r < 4; r++) c[mt][nt][r] = 0.f;

    // ---- stage 1 MMA: K=16 (cols 8..15 zero) ----
    {
        int k0 = (l & 3) * 2;
        uint32_t a[2][4];
#pragma unroll
        for (int mt = 0; mt < 2; mt++) {
            int r = w * 32 + mt * 16 + (l >> 2);
            a[mt][0] = *(const uint32_t*)&eas[r][k0];
            a[mt][1] = *(const uint32_t*)&eas[r + 8][k0];
            a[mt][2] = *(const uint32_t*)&eas[r][k0 + 8];
            a[mt][3] = *(const uint32_t*)&eas[r + 8][k0 + 8];
        }
#pragma unroll
        for (int nt = 0; nt < 8; nt++) {
            int nr = nt * 8 + (l >> 2);
            uint32_t b0 = *(const uint32_t*)&w1h[nr][k0];
            uint32_t b1 = *(const uint32_t*)&w1h[nr][k0 + 8];
            mma16816(c[0][nt], a[0], b0, b1);
            mma16816(c[1][nt], a[1], b0, b1);
        }
    }
    __syncthreads();   // all eas reads done before h1s overwrites buf

    // relu -> h1s (fp16), then reset accumulators
#pragma unroll
    for (int mt = 0; mt < 2; mt++) {
        int m = w * 32 + mt * 16 + (l >> 2);
#pragma unroll
        for (int nt = 0; nt < 8; nt++) {
            int n = nt * 8 + (l & 3) * 2;
            float v0 = c[mt][nt][0], v1 = c[mt][nt][1];
            float v2 = c[mt][nt][2], v3 = c[mt][nt][3];
            v0 = v0 > 0.f ? v0 : 0.f; v1 = v1 > 0.f ? v1 : 0.f;
            v2 = v2 > 0.f ? v2 : 0.f; v3 = v3 > 0.f ? v3 : 0.f;
            *(__half2*)&h1s[m][n]     = __floats2half2_rn(v0, v1);
            *(__half2*)&h1s[m + 8][n] = __floats2half2_rn(v2, v3);
            c[mt][nt][0] = 0.f; c[mt][nt][1] = 0.f;
            c[mt][nt][2] = 0.f; c[mt][nt][3] = 0.f;
        }
    }
    __syncthreads();

    // ---- stage 2 MMA: K=64 ----
#pragma unroll
    for (int kc = 0; kc < 4; kc++) {
        int k0 = kc * 16 + (l & 3) * 2;
        uint32_t a[2][4];
#pragma unroll
        for (int mt = 0; mt < 2; mt++) {
            int r = w * 32 + mt * 16 + (l >> 2);
            a[mt][0] = *(const uint32_t*)&h1s[r][k0];
            a[mt][1] = *(const uint32_t*)&h1s[r + 8][k0];
            a[mt][2] = *(const uint32_t*)&h1s[r][k0 + 8];
            a[mt][3] = *(const uint32_t*)&h1s[r + 8][k0 + 8];
        }
#pragma unroll
        for (int nt = 0; nt < 8; nt++) {
            int nr = nt * 8 + (l >> 2);
            uint32_t b0 = *(const uint32_t*)&w2s[nr][k0];
            uint32_t b1 = *(const uint32_t*)&w2s[nr][k0 + 8];
            mma16816(c[0][nt], a[0], b0, b1);
            mma16816(c[1][nt], a[1], b0, b1);
        }
    }

    // epilogue: relu -> fp16 -> scatter row to CSR slot (pos via shfl)
#pragma unroll
    for (int mt = 0; mt < 2; mt++) {
        int srcl = mt * 16 + (l >> 2);
        int pos0 = __shfl_sync(0xffffffffu, p_own, srcl);
        int pos1 = __shfl_sync(0xffffffffu, p_own, srcl + 8);
        size_t row0 = (size_t)pos0 * 64;
        size_t row1 = (size_t)pos1 * 64;
#pragma unroll
        for (int nt = 0; nt < 8; nt++) {
            int n = nt * 8 + (l & 3) * 2;
            float v0 = c[mt][nt][0], v1 = c[mt][nt][1];
            float v2 = c[mt][nt][2], v3 = c[mt][nt][3];
            v0 = v0 > 0.f ? v0 : 0.f; v1 = v1 > 0.f ? v1 : 0.f;
            v2 = v2 > 0.f ? v2 : 0.f; v3 = v3 > 0.f ? v3 : 0.f;
            *(__half2*)&g_ew[row0 + n] = __floats2half2_rn(v0, v1);
            *(__half2*)&g_ew[row1 + n] = __floats2half2_rn(v2, v3);
        }
    }
}

// ---------------- degree / dinv (warp per node, half2, unroll 2) ----------------
__global__ void __launch_bounds__(256) k_deg() {
    int w = (blockIdx.x * blockDim.x + threadIdx.x) >> 5;
    int lane = threadIdx.x & 31;
    if (w >= NN) return;
    int s = g_off[w], e = g_off[w + 1];
    const __half2* ewv = (const __half2*)g_ew;
    float2 d0 = make_float2(1.f, 1.f);
    float2 d1 = make_float2(0.f, 0.f);
    int p = s;
    for (; p + 2 <= e; p += 2) {
        float2 v0 = __half22float2(ewv[(size_t)p * 32 + lane]);
        float2 v1 = __half22float2(ewv[(size_t)(p + 1) * 32 + lane]);
        d0.x += v0.x; d0.y += v0.y;
        d1.x += v1.x; d1.y += v1.y;
    }
    if (p < e) {
        float2 v0 = __half22float2(ewv[(size_t)p * 32 + lane]);
        d0.x += v0.x; d0.y += v0.y;
    }
    float2 r; r.x = rsqrtf(d0.x + d1.x); r.y = rsqrtf(d0.y + d1.y);
    ((float2*)g_dinv)[(size_t)w * 32 + lane] = r;
}

// ---------------- aggregation (warp per node), unroll 4, int4 src, fp16 y ----------------
__global__ void __launch_bounds__(256) k_agg(const float* __restrict__ bc) {
    int w = (blockIdx.x * blockDim.x + threadIdx.x) >> 5;
    int lane = threadIdx.x & 31;
    if (w >= NN) return;
    int s = g_off[w], e = g_off[w + 1];
    const __half2* yv  = (const __half2*)g_y;
    const __half2* ewv = (const __half2*)g_ew;
    float2 a0 = __half22float2(yv[(size_t)w * 32 + lane]);   // self loop
    float2 a1 = make_float2(0.f, 0.f);
    float2 a2 = make_float2(0.f, 0.f);
    float2 a3 = make_float2(0.f, 0.f);
    int p = s;
    for (; p < e && (p & 3); p++) {
        int s0 = g_src[p];
        float2 f0 = __half22float2(ewv[(size_t)p * 32 + lane]);
        float2 y0 = __half22float2(yv[(size_t)s0 * 32 + lane]);
        a0.x = fmaf(f0.x, y0.x, a0.x); a0.y = fmaf(f0.y, y0.y, a0.y);
    }
    for (; p + 4 <= e; p += 4) {
        int4 sv = *(const int4*)&g_src[p];
        __half2 h0 = ewv[(size_t)p * 32 + lane];
        __half2 h1 = ewv[(size_t)(p + 1) * 32 + lane];
        __half2 h2 = ewv[(size_t)(p + 2) * 32 + lane];
        __half2 h3 = ewv[(size_t)(p + 3) * 32 + lane];
        float2 y0 = __half22float2(yv[(size_t)sv.x * 32 + lane]);
        float2 y1 = __half22float2(yv[(size_t)sv.y * 32 + lane]);
        float2 y2 = __half22float2(yv[(size_t)sv.z * 32 + lane]);
        float2 y3 = __half22float2(yv[(size_t)sv.w * 32 + lane]);
        float2 f0 = __half22float2(h0), f1 = __half22float2(h1);
        float2 f2 = __half22float2(h2), f3 = __half22float2(h3);
        a0.x = fmaf(f0.x, y0.x, a0.x); a0.y = fmaf(f0.y, y0.y, a0.y);
        a1.x = fmaf(f1.x, y1.x, a1.x); a1.y = fmaf(f1.y, y1.y, a1.y);
        a2.x = fmaf(f2.x, y2.x, a2.x); a2.y = fmaf(f2.y, y2.y, a2.y);
        a3.x = fmaf(f3.x, y3.x, a3.x); a3.y = fmaf(f3.y, y3.y, a3.y);
    }
    for (; p < e; p++) {
        int s0 = g_src[p];
        float2 f0 = __half22float2(ewv[(size_t)p * 32 + lane]);
        float2 y0 = __half22float2(yv[(size_t)s0 * 32 + lane]);
        a0.x = fmaf(f0.x, y0.x, a0.x); a0.y = fmaf(f0.y, y0.y, a0.y);
    }
    float2 dv = ((const float2*)g_dinv)[(size_t)w * 32 + lane];
    float2 r;
    r.x = fmaf(dv.x, (a0.x + a1.x) + (a2.x + a3.x), bc[2 * lane]);
    r.y = fmaf(dv.y, (a0.y + a1.y) + (a2.y + a3.y), bc[2 * lane + 1]);
    ((float2*)g_hagg)[(size_t)w * 32 + lane] = r;
}

// ---------------- tensor-core GEMM: C[N,64] = A[N,128] @ W[64,128]^T ----------------
__global__ void __launch_bounds__(256) k_gemm(const float* __restrict__ xin,
                                              const float* __restrict__ W,
                                              const float* __restrict__ bias,
                                              int mode,
                                              const float* __restrict__ ywc,
                                              const float* __restrict__ Wo,
                                              float* __restrict__ out) {
    __shared__ __half As[128][72];
    __shared__ __half Bs[64][136];
    int t = threadIdx.x;
    {   // vectorized W -> Bs (fp16)
        const float4* W4 = (const float4*)W;
        for (int i = t; i < 2048; i += 256) {
            float4 v = W4[i];
            int r = i >> 5, c4 = (i & 31) * 4;
            Bs[r][c4]     = __float2half(v.x);
            Bs[r][c4 + 1] = __float2half(v.y);
            Bs[r][c4 + 2] = __float2half(v.z);
            Bs[r][c4 + 3] = __float2half(v.w);
        }
    }

    const float *A0, *A1, *resid; float* C; int lda;
    if (mode == 0) { A0 = xin;    A1 = xin + 64; lda = 128; resid = 0;      C = g_xlin; }
    else           { A0 = g_xlin; A1 = g_hagg;   lda = 64;  resid = g_xlin; C = g_h;    }

    int bm = blockIdx.x * 128;
    int w = t >> 5, l = t & 31;
    float c[8][4];
#pragma unroll
    for (int nt = 0; nt < 8; nt++)
#pragma unroll
        for (int r = 0; r < 4; r++) c[nt][r] = 0.f;

    int lrow = t >> 1, lc0 = (t & 1) * 32;
    bool lvalid = (bm + lrow) < NN;

#pragma unroll
    for (int pass = 0; pass < 2; pass++) {
        const float* A = pass ? A1 : A0;
        __syncthreads();
        const float* srcp = &A[(size_t)(bm + lrow) * lda + lc0];
#pragma unroll
        for (int ch = 0; ch < 4; ch++) {
            float4 v0 = make_float4(0.f, 0.f, 0.f, 0.f), v1 = v0;
            if (lvalid) {
                v0 = *(const float4*)&srcp[ch * 8];
                v1 = *(const float4*)&srcp[ch * 8 + 4];
            }
            __half2 h0 = __floats2half2_rn(v0.x, v0.y);
            __half2 h1 = __floats2half2_rn(v0.z, v0.w);
            __half2 h2 = __floats2half2_rn(v1.x, v1.y);
            __half2 h3 = __floats2half2_rn(v1.z, v1.w);
            uint4 pk;
            pk.x = *(uint32_t*)&h0; pk.y = *(uint32_t*)&h1;
            pk.z = *(uint32_t*)&h2; pk.w = *(uint32_t*)&h3;
            *(uint4*)&As[lrow][lc0 + ch * 8] = pk;
        }
        __syncthreads();
#pragma unroll
        for (int kc = 0; kc < 4; kc++) {
            int k0 = kc * 16 + (l & 3) * 2;
            int row = w * 16 + (l >> 2);
            uint32_t a[4];
            a[0] = *(const uint32_t*)&As[row][k0];
            a[1] = *(const uint32_t*)&As[row + 8][k0];
            a[2] = *(const uint32_t*)&As[row][k0 + 8];
            a[3] = *(const uint32_t*)&As[row + 8][k0 + 8];
            int kb = pass * 64 + k0;
#pragma unroll
            for (int nt = 0; nt < 8; nt++) {
                int nr = nt * 8 + (l >> 2);
                uint32_t b0 = *(const uint32_t*)&Bs[nr][kb];
                uint32_t b1 = *(const uint32_t*)&Bs[nr][kb + 8];
                mma16816(c[nt], a, b0, b1);
            }
        }
    }

    int m0 = bm + w * 16 + (l >> 2);
    int n0 = (l & 3) * 2;

    if (Wo) {
        float oacc[2] = {0.f, 0.f};
#pragma unroll
        for (int nt = 0; nt < 8; nt++) {
            int n = nt * 8 + n0;
            float wx0 = Wo[n], wx1 = Wo[n + 1];
            float wh0 = Wo[64 + n], wh1 = Wo[64 + n + 1];
#pragma unroll
            for (int rr = 0; rr < 2; rr++) {
                int m = m0 + rr * 8;
                if (m >= NN) continue;
                float2 rv = *(const float2*)&resid[(size_t)m * 64 + n];
                float h0 = c[nt][rr * 2] + rv.x;
                float h1 = c[nt][rr * 2 + 1] + rv.y;
                h0 = h0 > 0.f ? h0 : 0.f;
                h1 = h1 > 0.f ? h1 : 0.f;
                oacc[rr] += rv.x * wx0 + rv.y * wx1 + h0 * wh0 + h1 * wh1;
            }
        }
#pragma unroll
        for (int rr = 0; rr < 2; rr++) {
            oacc[rr] += __shfl_xor_sync(0xffffffffu, oacc[rr], 1);
            oacc[rr] += __shfl_xor_sync(0xffffffffu, oacc[rr], 2);
        }
        if ((l & 3) == 0) {
            if (m0 < NN)     out[m0]     = oacc[0];
            if (m0 + 8 < NN) out[m0 + 8] = oacc[1];
        }
        return;
    }

#pragma unroll
    for (int nt = 0; nt < 8; nt++) {
        int n = nt * 8 + n0;
#pragma unroll
        for (int rr = 0; rr < 2; rr++) {
            int m = m0 + rr * 8;
            if (m >= NN) continue;
            float v0 = c[nt][rr * 2], v1 = c[nt][rr * 2 + 1];
            if (bias) { v0 += bias[n]; v1 += bias[n + 1]; }
            if (resid) {
                float2 rv = *(const float2*)&resid[(size_t)m * 64 + n];
                v0 += rv.x; v1 += rv.y;
            }
            float2 ov; ov.x = v0; ov.y = v1;
            *(float2*)&C[(size_t)m * 64 + n] = ov;
            if (ywc) {
                float2 dv = *(const float2*)&g_dinv[(size_t)m * 64 + n];
                float r0 = v0 > 0.f ? v0 : 0.f;
                float r1 = v1 > 0.f ? v1 : 0.f;
                *(__half2*)&g_y[(size_t)m * 64 + n] =
                    __floats2half2_rn(dv.x * r0 * ywc[n], dv.y * r1 * ywc[n + 1]);
            }
        }
    }
}

// ---------------- host ----------------
extern "C" void kernel_launch(void* const* d_in, const int* in_sizes, int n_in,
                              void* d_out, int out_size) {
    const float* x  = (const float*)d_in[0];
    const int*   ei = (const int*)d_in[1];     // int32 [2, E]
    const float* ea = (const float*)d_in[2];
    const float* W1 = (const float*)d_in[3];
    const float* W2 = (const float*)d_in[4];
    const float* Wi = (const float*)d_in[5];
    const float* bi = (const float*)d_in[6];
    const float* wc = (const float*)d_in[7];
    const float* bc = (const float*)d_in[8];
    const float* Wl = (const float*)d_in[9];
    const float* Wo = (const float*)d_in[10];
    float* out = (float*)d_out;

    const int WPB = 8;
    k_zero<<<(NN + 1023) / 1024, 1024>>>();
    k_count<<<(NE + 255) / 256, 256>>>(ei);
    k_scan_sum<<<NBLK, 1024>>>();
    k_scan_top<<<1, 128>>>();
    k_scan_apply<<<NBLK, 1024>>>();
    k_fill<<<(NE + 255) / 256, 256>>>(ei);
    k_ew<<<NE / 256, 256>>>(ea, W1, W2);
    k_deg<<<(NN + WPB - 1) / WPB, 256>>>();
    k_gemm<<<(NN + 127) / 128, 256>>>(x, Wi, bi, 0, wc, nullptr, nullptr);
    for (int l = 0; l < 3; l++) {
        k_agg<<<(NN + WPB - 1) / WPB, 256>>>(bc + l * 64);
        k_gemm<<<(NN + 127) / 128, 256>>>(x, Wl + l * 64 * 128, nullptr, 1,
                                          l < 2 ? wc + (l + 1) * 64 : nullptr,
                                          l == 2 ? Wo : nullptr,
                                          l == 2 ? out : nullptr);
    }
}